// round 8
// baseline (speedup 1.0000x reference)
#include <cuda_runtime.h>
#include <cuda_bf16.h>
#include <cstdint>

#define BB   128
#define TT   1024
#define II   256
#define HH   256
#define G4   1024           // 4*H

typedef unsigned long long ull;

// ---------------- device scratch ----------------
__device__ float g_xp[(size_t)TT * G4 * BB];   // [t][g][u][b]
__device__ float g_y0[(size_t)TT * HH * BB];   // [t][u][b]  layer0 out (GEMM-1 input)
__device__ float g_h[2][BB * HH];              // ping-pong h, [b][u]

// ---------------- f32x2 packed-FMA helpers ----------------
__device__ __forceinline__ void ffma2(ull &d, ull a, ull b) {
    asm("fma.rn.f32x2 %0, %1, %2, %0;" : "+l"(d) : "l"(a), "l"(b));
}
__device__ __forceinline__ ull dup2(float x) {
    ull r; asm("mov.b64 %0, {%1, %1};" : "=l"(r) : "f"(x)); return r;
}
__device__ __forceinline__ float2 unpack2(ull v) {
    float2 r; asm("mov.b64 {%0, %1}, %2;" : "=f"(r.x), "=f"(r.y) : "l"(v)); return r;
}

// ---------------- cp.async helpers ----------------
__device__ __forceinline__ void cp_async16(uint32_t saddr, const void* g) {
    asm volatile("cp.async.cg.shared.global [%0], [%1], 16;" :: "r"(saddr), "l"(g));
}
#define CP_COMMIT()  asm volatile("cp.async.commit_group;" ::: "memory")
#define CP_WAIT(n)   asm volatile("cp.async.wait_group %0;" :: "n"(n) : "memory")

#define CLUSTER_ARRIVE() asm volatile("barrier.cluster.arrive.aligned;" ::: "memory")
#define CLUSTER_WAIT()   asm volatile("barrier.cluster.wait.aligned;"   ::: "memory")

// ---------------- fast activations ----------------
__device__ __forceinline__ float fast_exp2(float x) {
    x = fminf(fmaxf(x, -126.0f), 126.0f);
    float r = rintf(x);
    float f = x - r;
    float p = 1.535336188319500e-4f;
    p = fmaf(p, f, 1.339887440266574e-3f);
    p = fmaf(p, f, 9.618437357674640e-3f);
    p = fmaf(p, f, 5.550332471162809e-2f);
    p = fmaf(p, f, 2.402264791363012e-1f);
    p = fmaf(p, f, 6.931472028550421e-1f);
    p = fmaf(p, f, 1.0f);
    return __int_as_float(__float_as_int(p) + ((int)r << 23));
}
__device__ __forceinline__ float fast_sigmoid(float x) {
    float e = fast_exp2(-1.4426950408889634f * x);
    return __fdividef(1.0f, 1.0f + e);
}
__device__ __forceinline__ float fast_tanh(float x) {
    float e = fast_exp2(-2.8853900817779268f * x);
    return __fdividef(2.0f, 1.0f + e) - 1.0f;
}

// ---------------- init: zero h ping-pong ----------------
__global__ void init_kernel() {
    int i = blockIdx.x * 256 + threadIdx.x;       // 16384 threads
    float* h = (float*)g_h;
    for (int j = i; j < 2 * HH * BB; j += 16384) h[j] = 0.0f;
}

// ---------------- input-projection GEMM, reg double-buffered ----------------
// xp[t][j][b] = sum_k W[j,k] * A_t[k,b] + b_ih[j] + b_hh[j]
template<int MODE>
__global__ __launch_bounds__(256) void gemm_xp_kernel(
    const float* __restrict__ A,
    const float* __restrict__ W,
    const float* __restrict__ bih,
    const float* __restrict__ bhh)
{
    const int t  = blockIdx.y;
    const int jt = blockIdx.x;            // 0..7
    __shared__ __align__(16) float sW[16][128];
    __shared__ __align__(16) float sA[16][132];
    const int tid = threadIdx.x;
    const int tx = tid & 15, ty = tid >> 4;

    const float* Ap = (MODE == 0) ? A : (const float*)g_y0;

    ull acc[8][4];
    #pragma unroll
    for (int i = 0; i < 8; i++)
        #pragma unroll
        for (int j = 0; j < 4; j++) acc[i][j] = 0ULL;

    float4 wreg[2], areg[2];

    auto load_tile = [&](int k0) {
        #pragma unroll
        for (int q = 0; q < 2; q++) {
            int l = tid * 2 + q;
            int row = l >> 2;
            int kc  = (l & 3) * 4;
            wreg[q] = *(const float4*)&W[(size_t)(jt * 128 + row) * 256 + k0 + kc];
            if (MODE == 0) {
                int bb = l >> 2;
                areg[q] = *(const float4*)&Ap[((size_t)bb * TT + t) * II + k0 + kc];
            } else {
                int kk = l >> 5;
                int bc = (l & 31) * 4;
                areg[q] = *(const float4*)&Ap[((size_t)t * HH + k0 + kk) * BB + bc];
            }
        }
    };
    auto store_tile = [&]() {
        #pragma unroll
        for (int q = 0; q < 2; q++) {
            int l = tid * 2 + q;
            int row = l >> 2;
            int kc  = (l & 3) * 4;
            sW[kc + 0][row] = wreg[q].x; sW[kc + 1][row] = wreg[q].y;
            sW[kc + 2][row] = wreg[q].z; sW[kc + 3][row] = wreg[q].w;
            if (MODE == 0) {
                int bb = l >> 2;
                sA[kc + 0][bb] = areg[q].x; sA[kc + 1][bb] = areg[q].y;
                sA[kc + 2][bb] = areg[q].z; sA[kc + 3][bb] = areg[q].w;
            } else {
                int kk = l >> 5;
                int bc = (l & 31) * 4;
                *(float4*)&sA[kk][bc] = areg[q];
            }
        }
    };

    load_tile(0);
    for (int k0 = 0; k0 < 256; k0 += 16) {
        store_tile();
        __syncthreads();
        if (k0 + 16 < 256) load_tile(k0 + 16);   // LDGs in flight during compute
        #pragma unroll
        for (int k = 0; k < 16; k++) {
            float4 w0 = *(const float4*)&sW[k][ty * 4];
            float4 w1 = *(const float4*)&sW[k][64 + ty * 4];
            ulonglong2 a0 = *(const ulonglong2*)&sA[k][tx * 4];
            ulonglong2 a1 = *(const ulonglong2*)&sA[k][64 + tx * 4];
            ull av0 = a0.x, av1 = a0.y, av2 = a1.x, av3 = a1.y;
            float wf[8] = {w0.x, w0.y, w0.z, w0.w, w1.x, w1.y, w1.z, w1.w};
            #pragma unroll
            for (int i = 0; i < 8; i++) {
                ull wd = dup2(wf[i]);
                ffma2(acc[i][0], wd, av0);
                ffma2(acc[i][1], wd, av1);
                ffma2(acc[i][2], wd, av2);
                ffma2(acc[i][3], wd, av3);
            }
        }
        __syncthreads();
    }

    #pragma unroll
    for (int i = 0; i < 8; i++) {
        int jloc = (i < 4) ? (ty * 4 + i) : (64 + ty * 4 + (i - 4));
        int j = jt * 128 + jloc;
        float bsum = bih[j] + bhh[j];
        float2 p0 = unpack2(acc[i][0]);
        float2 p1 = unpack2(acc[i][1]);
        float2 p2 = unpack2(acc[i][2]);
        float2 p3 = unpack2(acc[i][3]);
        float4 o0 = make_float4(p0.x + bsum, p0.y + bsum, p1.x + bsum, p1.y + bsum);
        float4 o1 = make_float4(p2.x + bsum, p2.y + bsum, p3.x + bsum, p3.y + bsum);
        size_t base = ((size_t)t * G4 + j) * BB;
        *(float4*)&g_xp[base + tx * 4]      = o0;
        *(float4*)&g_xp[base + 64 + tx * 4] = o1;
    }
}

// ---------------- persistent recurrent kernel: clusters ----------------
// grid 128 = 16 bt-groups x 8 ut.  Cluster (8,1,1) = the 8 ut-blocks of one bt
// group (consecutive blockIdx).  Block owns 32 units x 8 batches, 256 threads.
// Inter-block sync = barrier.cluster (release/acquire covers global h stores).
#define SW_U   1044           // per-u float stride in sW (4 gates x 260 + 4)
#define SW_G   260
#define SH_ROW 260            // per-b float stride in sH
#define SO0_ROW 12            // layer0 staging row stride (u-major)
#define SO1_ROW 36            // layer1 / h staging row stride (b-major)

template<int LAYER>
__global__ __launch_bounds__(256) __cluster_dims__(8, 1, 1)
void lstm_rec_kernel(
    const float* __restrict__ Whh,        // layer slice [4*256, 256]
    const float* __restrict__ masks,      // layer slice [3,128,256]
    float* __restrict__ out1)             // only used for LAYER==1: out [b][t][u]
{
    extern __shared__ float smem[];
    float* sW   = smem;                        // 32 * 1044
    float* sH   = smem + 32 * SW_U;            // 8 * 260
    float* sOut = sH + 8 * SH_ROW;             // 384 floats
    float* sHn  = sOut + 384;                  // 8 * 36

    const int tid = threadIdx.x;
    const int u_l = tid >> 3;                  // 0..31
    const int b_l = tid & 7;                   // 0..7
    const int bt  = blockIdx.x >> 3;           // 0..15 (cluster id)
    const int ut  = blockIdx.x & 7;            // 0..7  (cluster rank)
    const int u_g = ut * 32 + u_l;
    const int b_g = bt * 8 + b_l;

    float* yout = (LAYER == 0) ? g_y0 : out1;  // device-side symbol resolution

    // ---- load W_hh tile: [u_l][gate][k], padded ----
    for (int i = tid; i < 32 * 4 * 256; i += 256) {
        int uu = i >> 10;
        int g  = (i >> 8) & 3;
        int k  = i & 255;
        sW[uu * SW_U + g * SW_G + k] = Whh[(size_t)(g * HH + ut * 32 + uu) * HH + k];
    }
    const float om = masks[(size_t)(0 * BB + b_g) * HH + u_g];
    const float hm = masks[(size_t)(1 * BB + b_g) * HH + u_g];
    const float cm = masks[(size_t)(2 * BB + b_g) * HH + u_g];
    float c = 0.0f;
    __syncthreads();

    const uint32_t sH_base = (uint32_t)__cvta_generic_to_shared(sH);
    const float* wrow = &sW[u_l * SW_U];

    // cp.async: 32 threads per row of 8, each owns 4 floats... assignment:
    // thread = (row, ch): row = tid>>5 (0..7), ch = tid&31 (0..31); 16B each.
    const int cp_row = tid >> 5;
    const int cp_ch  = tid & 31;

    // ---- initial xp prefetch (t = 0) ----
    float xi, xf, xg, xo;
    {
        size_t xb = (size_t)b_g;
        xi = __ldcs(&g_xp[xb + (size_t)(0 * HH + u_g) * BB]);
        xf = __ldcs(&g_xp[xb + (size_t)(1 * HH + u_g) * BB]);
        xg = __ldcs(&g_xp[xb + (size_t)(2 * HH + u_g) * BB]);
        xo = __ldcs(&g_xp[xb + (size_t)(3 * HH + u_g) * BB]);
    }

    for (int t = 0; t < TT; t++) {
        // ---- stage h rows [b_g][0..255] in two k-halves ----
        const float* hsrc = g_h[t & 1];
        cp_async16(sH_base + (cp_row * SH_ROW + cp_ch * 4) * 4,
                   &hsrc[(size_t)(bt * 8 + cp_row) * HH + cp_ch * 4]);
        CP_COMMIT();
        cp_async16(sH_base + (cp_row * SH_ROW + 128 + cp_ch * 4) * 4,
                   &hsrc[(size_t)(bt * 8 + cp_row) * HH + 128 + cp_ch * 4]);
        CP_COMMIT();

        ull ai2 = 0ULL, af2 = 0ULL, ag2 = 0ULL, ao2 = 0ULL;

        CP_WAIT(1);
        __syncthreads();                       // first k-half ready
        #pragma unroll 8
        for (int k = 0; k < 128; k += 4) {
            ulonglong2 h4 = *(const ulonglong2*)&sH[b_l * SH_ROW + k];
            ulonglong2 wi = *(const ulonglong2*)&wrow[0 * SW_G + k];
            ulonglong2 wf = *(const ulonglong2*)&wrow[1 * SW_G + k];
            ulonglong2 wg = *(const ulonglong2*)&wrow[2 * SW_G + k];
            ulonglong2 wo = *(const ulonglong2*)&wrow[3 * SW_G + k];
            ffma2(ai2, wi.x, h4.x); ffma2(ai2, wi.y, h4.y);
            ffma2(af2, wf.x, h4.x); ffma2(af2, wf.y, h4.y);
            ffma2(ag2, wg.x, h4.x); ffma2(ag2, wg.y, h4.y);
            ffma2(ao2, wo.x, h4.x); ffma2(ao2, wo.y, h4.y);
        }
        CP_WAIT(0);
        __syncthreads();                       // second k-half ready
        #pragma unroll 8
        for (int k = 128; k < 256; k += 4) {
            ulonglong2 h4 = *(const ulonglong2*)&sH[b_l * SH_ROW + k];
            ulonglong2 wi = *(const ulonglong2*)&wrow[0 * SW_G + k];
            ulonglong2 wf = *(const ulonglong2*)&wrow[1 * SW_G + k];
            ulonglong2 wg = *(const ulonglong2*)&wrow[2 * SW_G + k];
            ulonglong2 wo = *(const ulonglong2*)&wrow[3 * SW_G + k];
            ffma2(ai2, wi.x, h4.x); ffma2(ai2, wi.y, h4.y);
            ffma2(af2, wf.x, h4.x); ffma2(af2, wf.y, h4.y);
            ffma2(ag2, wg.x, h4.x); ffma2(ag2, wg.y, h4.y);
            ffma2(ao2, wo.x, h4.x); ffma2(ao2, wo.y, h4.y);
        }

        float2 pi = unpack2(ai2), pf = unpack2(af2);
        float2 pg = unpack2(ag2), po = unpack2(ao2);
        float ai = pi.x + pi.y + xi;
        float af = pf.x + pf.y + xf;
        float ag = pg.x + pg.y + xg;
        float ao = po.x + po.y + xo;

        float si = fast_sigmoid(ai);
        float sf = fast_sigmoid(af);
        float so = fast_sigmoid(ao);
        float tg = fast_tanh(ag);
        float c2 = fmaf(sf, c, si * tg);
        float h2 = so * fast_tanh(c2);
        c = c2 * cm;

        // ---- stage outputs for coalesced writes ----
        if (LAYER == 0) sOut[u_l * SO0_ROW + b_l] = h2 * om;  // y0[t][u][b]
        else            sOut[b_l * SO1_ROW + u_l] = h2 * om;  // out[b][t][u]
        sHn[b_l * SO1_ROW + u_l] = h2 * hm;                   // g_h[b][u]
        __syncthreads();

        if (tid < 64) {                        // y / out
            if (LAYER == 0) {
                int u = tid >> 1, q = tid & 1;
                float4 v = *(const float4*)&sOut[u * SO0_ROW + q * 4];
                *(float4*)&yout[((size_t)t * HH + ut * 32 + u) * BB + bt * 8 + q * 4] = v;
            } else {
                int r = tid >> 3, q = tid & 7;
                float4 v = *(const float4*)&sOut[r * SO1_ROW + q * 4];
                *(float4*)&yout[((size_t)(bt * 8 + r) * TT + t) * HH + ut * 32 + q * 4] = v;
            }
        } else if (tid < 128) {                // next h
            int w = tid - 64;
            int r = w >> 3, q = w & 7;
            float4 v = *(const float4*)&sHn[r * SO1_ROW + q * 4];
            *(float4*)&g_h[(t + 1) & 1][(size_t)(bt * 8 + r) * HH + ut * 32 + q * 4] = v;
        }

        // ---- prefetch xp(t+1) while the barrier drains ----
        {
            int tn = (t + 1 < TT) ? (t + 1) : t;
            size_t xb = (size_t)tn * (size_t)G4 * BB + b_g;
            xi = __ldcs(&g_xp[xb + (size_t)(0 * HH + u_g) * BB]);
            xf = __ldcs(&g_xp[xb + (size_t)(1 * HH + u_g) * BB]);
            xg = __ldcs(&g_xp[xb + (size_t)(2 * HH + u_g) * BB]);
            xo = __ldcs(&g_xp[xb + (size_t)(3 * HH + u_g) * BB]);
        }

        // ---- cluster barrier (release -> acquire; covers global h stores) ----
        CLUSTER_ARRIVE();
        CLUSTER_WAIT();
    }
}

// ---------------- launch ----------------
extern "C" void kernel_launch(void* const* d_in, const int* in_sizes, int n_in,
                              void* d_out, int out_size) {
    const float* x     = (const float*)d_in[0];   // [128,1024,256]
    const float* W_ih  = (const float*)d_in[1];   // [2,1024,256]
    const float* W_hh  = (const float*)d_in[2];   // [2,1024,256]
    const float* b_ih  = (const float*)d_in[3];   // [2,1024]
    const float* b_hh  = (const float*)d_in[4];   // [2,1024]
    const float* masks = (const float*)d_in[5];   // [2,3,128,256]
    float* out = (float*)d_out;

    const int rec_smem = (32 * SW_U + 8 * SH_ROW + 384 + 8 * SO1_ROW) * (int)sizeof(float);
    cudaFuncSetAttribute(lstm_rec_kernel<0>,
                         cudaFuncAttributeMaxDynamicSharedMemorySize, rec_smem);
    cudaFuncSetAttribute(lstm_rec_kernel<1>,
                         cudaFuncAttributeMaxDynamicSharedMemorySize, rec_smem);

    dim3 ggrid(8, TT);

    // ---- layer 0 ----  (gemm first so ncu's first-node capture is useful)
    gemm_xp_kernel<0><<<ggrid, 256>>>(x, W_ih, b_ih, b_hh);
    init_kernel<<<64, 256>>>();
    lstm_rec_kernel<0><<<128, 256, rec_smem>>>(W_hh, masks, nullptr);

    // ---- layer 1 ----
    gemm_xp_kernel<1><<<ggrid, 256>>>(nullptr, W_ih + (size_t)G4 * II,
                                      b_ih + G4, b_hh + G4);
    init_kernel<<<64, 256>>>();
    lstm_rec_kernel<1><<<128, 256, rec_smem>>>(W_hh + (size_t)G4 * HH,
                                               masks + (size_t)3 * BB * HH, out);
}

// round 9
// speedup vs baseline: 1.6654x; 1.6654x over previous
#include <cuda_runtime.h>
#include <cuda_bf16.h>
#include <cstdint>

#define BB   128
#define TT   1024
#define II   256
#define HH   256
#define G4   1024           // 4*H
#define NBLK 128

typedef unsigned long long ull;

// ---------------- device scratch ----------------
__device__ float g_xp[(size_t)TT * G4 * BB];   // [t][g][u][b]
__device__ float g_y0[(size_t)TT * HH * BB];   // [t][u][b]  layer0 out (GEMM-1 input)
__device__ float g_h[2][BB * HH];              // ping-pong h, [b][u]
__device__ unsigned g_arrive[8 * 32];          // 8 group counters, 128B apart

// ---------------- f32x2 packed-FMA helpers ----------------
__device__ __forceinline__ void ffma2(ull &d, ull a, ull b) {
    asm("fma.rn.f32x2 %0, %1, %2, %0;" : "+l"(d) : "l"(a), "l"(b));
}
__device__ __forceinline__ ull dup2(float x) {
    ull r; asm("mov.b64 %0, {%1, %1};" : "=l"(r) : "f"(x)); return r;
}
__device__ __forceinline__ float2 unpack2(ull v) {
    float2 r; asm("mov.b64 {%0, %1}, %2;" : "=f"(r.x), "=f"(r.y) : "l"(v)); return r;
}

// ---------------- cp.async helpers ----------------
__device__ __forceinline__ void cp_async16(uint32_t saddr, const void* g) {
    asm volatile("cp.async.cg.shared.global [%0], [%1], 16;" :: "r"(saddr), "l"(g));
}
#define CP_COMMIT()  asm volatile("cp.async.commit_group;" ::: "memory")
#define CP_WAIT(n)   asm volatile("cp.async.wait_group %0;" :: "n"(n) : "memory")

// ---------------- fast activations ----------------
__device__ __forceinline__ float fast_exp2(float x) {
    x = fminf(fmaxf(x, -126.0f), 126.0f);
    float r = rintf(x);
    float f = x - r;
    float p = 1.535336188319500e-4f;
    p = fmaf(p, f, 1.339887440266574e-3f);
    p = fmaf(p, f, 9.618437357674640e-3f);
    p = fmaf(p, f, 5.550332471162809e-2f);
    p = fmaf(p, f, 2.402264791363012e-1f);
    p = fmaf(p, f, 6.931472028550421e-1f);
    p = fmaf(p, f, 1.0f);
    return __int_as_float(__float_as_int(p) + ((int)r << 23));
}
__device__ __forceinline__ float fast_sigmoid(float x) {
    float e = fast_exp2(-1.4426950408889634f * x);
    return __fdividef(1.0f, 1.0f + e);
}
__device__ __forceinline__ float fast_tanh(float x) {
    float e = fast_exp2(-2.8853900817779268f * x);
    return __fdividef(2.0f, 1.0f + e) - 1.0f;
}

// ---------------- init: zero h ping-pong + arrival counters ----------------
__global__ void init_kernel() {
    int i = blockIdx.x * 256 + threadIdx.x;       // 16384 threads
    float* h = (float*)g_h;
    for (int j = i; j < 2 * HH * BB; j += 16384) h[j] = 0.0f;
    if (i < 8 * 32) g_arrive[i] = 0u;
}

// ---------------- input-projection GEMM, reg double-buffered (R8, 74% fma) ----
// xp[t][j][b] = sum_k W[j,k] * A_t[k,b] + b_ih[j] + b_hh[j]
template<int MODE>
__global__ __launch_bounds__(256) void gemm_xp_kernel(
    const float* __restrict__ A,
    const float* __restrict__ W,
    const float* __restrict__ bih,
    const float* __restrict__ bhh)
{
    const int t  = blockIdx.y;
    const int jt = blockIdx.x;            // 0..7
    __shared__ __align__(16) float sW[16][128];
    __shared__ __align__(16) float sA[16][132];
    const int tid = threadIdx.x;
    const int tx = tid & 15, ty = tid >> 4;

    const float* Ap = (MODE == 0) ? A : (const float*)g_y0;

    ull acc[8][4];
    #pragma unroll
    for (int i = 0; i < 8; i++)
        #pragma unroll
        for (int j = 0; j < 4; j++) acc[i][j] = 0ULL;

    float4 wreg[2], areg[2];

    auto load_tile = [&](int k0) {
        #pragma unroll
        for (int q = 0; q < 2; q++) {
            int l = tid * 2 + q;
            int row = l >> 2;
            int kc  = (l & 3) * 4;
            wreg[q] = *(const float4*)&W[(size_t)(jt * 128 + row) * 256 + k0 + kc];
            if (MODE == 0) {
                int bb = l >> 2;
                areg[q] = *(const float4*)&Ap[((size_t)bb * TT + t) * II + k0 + kc];
            } else {
                int kk = l >> 5;
                int bc = (l & 31) * 4;
                areg[q] = *(const float4*)&Ap[((size_t)t * HH + k0 + kk) * BB + bc];
            }
        }
    };
    auto store_tile = [&]() {
        #pragma unroll
        for (int q = 0; q < 2; q++) {
            int l = tid * 2 + q;
            int row = l >> 2;
            int kc  = (l & 3) * 4;
            sW[kc + 0][row] = wreg[q].x; sW[kc + 1][row] = wreg[q].y;
            sW[kc + 2][row] = wreg[q].z; sW[kc + 3][row] = wreg[q].w;
            if (MODE == 0) {
                int bb = l >> 2;
                sA[kc + 0][bb] = areg[q].x; sA[kc + 1][bb] = areg[q].y;
                sA[kc + 2][bb] = areg[q].z; sA[kc + 3][bb] = areg[q].w;
            } else {
                int kk = l >> 5;
                int bc = (l & 31) * 4;
                *(float4*)&sA[kk][bc] = areg[q];
            }
        }
    };

    load_tile(0);
    for (int k0 = 0; k0 < 256; k0 += 16) {
        store_tile();
        __syncthreads();
        if (k0 + 16 < 256) load_tile(k0 + 16);   // LDGs in flight during compute
        #pragma unroll
        for (int k = 0; k < 16; k++) {
            float4 w0 = *(const float4*)&sW[k][ty * 4];
            float4 w1 = *(const float4*)&sW[k][64 + ty * 4];
            ulonglong2 a0 = *(const ulonglong2*)&sA[k][tx * 4];
            ulonglong2 a1 = *(const ulonglong2*)&sA[k][64 + tx * 4];
            ull av0 = a0.x, av1 = a0.y, av2 = a1.x, av3 = a1.y;
            float wf[8] = {w0.x, w0.y, w0.z, w0.w, w1.x, w1.y, w1.z, w1.w};
            #pragma unroll
            for (int i = 0; i < 8; i++) {
                ull wd = dup2(wf[i]);
                ffma2(acc[i][0], wd, av0);
                ffma2(acc[i][1], wd, av1);
                ffma2(acc[i][2], wd, av2);
                ffma2(acc[i][3], wd, av3);
            }
        }
        __syncthreads();
    }

    #pragma unroll
    for (int i = 0; i < 8; i++) {
        int jloc = (i < 4) ? (ty * 4 + i) : (64 + ty * 4 + (i - 4));
        int j = jt * 128 + jloc;
        float bsum = bih[j] + bhh[j];
        float2 p0 = unpack2(acc[i][0]);
        float2 p1 = unpack2(acc[i][1]);
        float2 p2 = unpack2(acc[i][2]);
        float2 p3 = unpack2(acc[i][3]);
        float4 o0 = make_float4(p0.x + bsum, p0.y + bsum, p1.x + bsum, p1.y + bsum);
        float4 o1 = make_float4(p2.x + bsum, p2.y + bsum, p3.x + bsum, p3.y + bsum);
        size_t base = ((size_t)t * G4 + j) * BB;
        *(float4*)&g_xp[base + tx * 4]      = o0;
        *(float4*)&g_xp[base + 64 + tx * 4] = o1;
    }
}

// ---------------- persistent recurrent kernel: R7 proven design ----------------
// grid 128 = 8 bt-groups x 16 ut.  Block owns 16 units x 16 batches.
// Barrier: per-bt-group red.release counter + single acquire poll (NO cluster
// barrier — barrier.cluster emits CCTL.IVALL per step and regressed 2x in R8).
#define SW_U   1044           // per-u float stride in sW (4 gates x 260 + 4)
#define SW_G   260
#define SH_ROW 260            // per-b float stride in sH
#define SO_ROW 20             // staging row stride

template<int LAYER>
__global__ __launch_bounds__(256) void lstm_rec_kernel(
    const float* __restrict__ Whh,        // layer slice [4*256, 256]
    const float* __restrict__ masks,      // layer slice [3,128,256]
    float* __restrict__ out1)             // only used for LAYER==1: out [b][t][u]
{
    extern __shared__ float smem[];
    float* sW   = smem;                        // 16 * 1044
    float* sH   = smem + 16 * SW_U;            // 16 * 260
    float* sOut = sH + 16 * SH_ROW;            // 16 * 20
    float* sHn  = sOut + 16 * SO_ROW;          // 16 * 20

    const int tid = threadIdx.x;
    const int u_l = tid >> 4;                  // 0..15
    const int b_l = tid & 15;                  // 0..15
    const int bt  = blockIdx.x >> 4;           // 0..7  (barrier group)
    const int ut  = blockIdx.x & 15;           // 0..15
    const int u_g = ut * 16 + u_l;
    const int b_g = bt * 16 + b_l;

    float* yout = (LAYER == 0) ? g_y0 : out1;  // device-side symbol resolution

    // ---- load W_hh tile: [u_l][gate][k], padded ----
    for (int i = tid; i < 16 * 4 * 256; i += 256) {
        int uu = i >> 10;
        int g  = (i >> 8) & 3;
        int k  = i & 255;
        sW[uu * SW_U + g * SW_G + k] = Whh[(size_t)(g * HH + ut * 16 + uu) * HH + k];
    }
    const float om = masks[(size_t)(0 * BB + b_g) * HH + u_g];
    const float hm = masks[(size_t)(1 * BB + b_g) * HH + u_g];
    const float cm = masks[(size_t)(2 * BB + b_g) * HH + u_g];
    float c = 0.0f;
    __syncthreads();

    const uint32_t sH_base = (uint32_t)__cvta_generic_to_shared(sH);
    const float* wrow = &sW[u_l * SW_U];
    volatile unsigned* ctr = &g_arrive[bt * 32];

    // cp.async assignment: 8 threads per row, each owns 16 floats (4x16B)
    const int cp_row = (tid & 127) >> 3;       // 0..15
    const int cp_ch  = (tid & 7);              // 0..7  -> floats cp_ch*16 .. +15

    for (int t = 0; t < TT; t++) {
        // ---- xp prefetch: 4 gates, coalesced 64B runs per (g,u) ----
        size_t xb = (size_t)t * (size_t)G4 * BB + b_g;
        float xi = __ldcs(&g_xp[xb + (size_t)(0 * HH + u_g) * BB]);
        float xf = __ldcs(&g_xp[xb + (size_t)(1 * HH + u_g) * BB]);
        float xg = __ldcs(&g_xp[xb + (size_t)(2 * HH + u_g) * BB]);
        float xo = __ldcs(&g_xp[xb + (size_t)(3 * HH + u_g) * BB]);

        // ---- stage h rows [b_g][0..255] in two k-halves ----
        const float* hsrc = g_h[t & 1];
        if (tid < 128) {
            int fo = cp_ch * 16;                          // float offset in k-half 0
            #pragma unroll
            for (int q = 0; q < 4; q++)
                cp_async16(sH_base + (cp_row * SH_ROW + fo + q * 4) * 4,
                           &hsrc[(size_t)(bt * 16 + cp_row) * HH + fo + q * 4]);
        }
        CP_COMMIT();
        if (tid >= 128) {
            int fo = 128 + cp_ch * 16;                    // float offset in k-half 1
            #pragma unroll
            for (int q = 0; q < 4; q++)
                cp_async16(sH_base + (cp_row * SH_ROW + fo + q * 4) * 4,
                           &hsrc[(size_t)(bt * 16 + cp_row) * HH + fo + q * 4]);
        }
        CP_COMMIT();

        ull ai2 = 0ULL, af2 = 0ULL, ag2 = 0ULL, ao2 = 0ULL;

        CP_WAIT(1);
        __syncthreads();                       // first k-half ready
        #pragma unroll 8
        for (int k = 0; k < 128; k += 4) {
            ulonglong2 h4 = *(const ulonglong2*)&sH[b_l * SH_ROW + k];
            ulonglong2 wi = *(const ulonglong2*)&wrow[0 * SW_G + k];
            ulonglong2 wf = *(const ulonglong2*)&wrow[1 * SW_G + k];
            ulonglong2 wg = *(const ulonglong2*)&wrow[2 * SW_G + k];
            ulonglong2 wo = *(const ulonglong2*)&wrow[3 * SW_G + k];
            ffma2(ai2, wi.x, h4.x); ffma2(ai2, wi.y, h4.y);
            ffma2(af2, wf.x, h4.x); ffma2(af2, wf.y, h4.y);
            ffma2(ag2, wg.x, h4.x); ffma2(ag2, wg.y, h4.y);
            ffma2(ao2, wo.x, h4.x); ffma2(ao2, wo.y, h4.y);
        }
        CP_WAIT(0);
        __syncthreads();                       // second k-half ready
        #pragma unroll 8
        for (int k = 128; k < 256; k += 4) {
            ulonglong2 h4 = *(const ulonglong2*)&sH[b_l * SH_ROW + k];
            ulonglong2 wi = *(const ulonglong2*)&wrow[0 * SW_G + k];
            ulonglong2 wf = *(const ulonglong2*)&wrow[1 * SW_G + k];
            ulonglong2 wg = *(const ulonglong2*)&wrow[2 * SW_G + k];
            ulonglong2 wo = *(const ulonglong2*)&wrow[3 * SW_G + k];
            ffma2(ai2, wi.x, h4.x); ffma2(ai2, wi.y, h4.y);
            ffma2(af2, wf.x, h4.x); ffma2(af2, wf.y, h4.y);
            ffma2(ag2, wg.x, h4.x); ffma2(ag2, wg.y, h4.y);
            ffma2(ao2, wo.x, h4.x); ffma2(ao2, wo.y, h4.y);
        }

        float2 pi = unpack2(ai2), pf = unpack2(af2);
        float2 pg = unpack2(ag2), po = unpack2(ao2);
        float ai = pi.x + pi.y + xi;
        float af = pf.x + pf.y + xf;
        float ag = pg.x + pg.y + xg;
        float ao = po.x + po.y + xo;

        float si = fast_sigmoid(ai);
        float sf = fast_sigmoid(af);
        float so = fast_sigmoid(ao);
        float tg = fast_tanh(ag);
        float c2 = fmaf(sf, c, si * tg);
        float h2 = so * fast_tanh(c2);
        c = c2 * cm;

        // ---- stage outputs for coalesced writes ----
        if (LAYER == 0) sOut[u_l * SO_ROW + b_l] = h2 * om;   // y0[t][u][b]
        else            sOut[b_l * SO_ROW + u_l] = h2 * om;   // out[b][t][u]
        sHn[b_l * SO_ROW + u_l] = h2 * hm;                    // g_h[b][u]
        __syncthreads();

        if (tid < 64) {                        // y / out
            int r = tid >> 2, cc = tid & 3;
            float4 v = *(const float4*)&sOut[r * SO_ROW + cc * 4];
            if (LAYER == 0)
                *(float4*)&yout[((size_t)t * HH + ut * 16 + r) * BB + bt * 16 + cc * 4] = v;
            else
                *(float4*)&yout[((size_t)(bt * 16 + r) * TT + t) * HH + ut * 16 + cc * 4] = v;
        } else if (tid < 128) {                // next h
            int w = tid - 64;
            int r = w >> 2, cc = w & 3;
            float4 v = *(const float4*)&sHn[r * SO_ROW + cc * 4];
            *(float4*)&g_h[(t + 1) & 1][(size_t)(bt * 16 + r) * HH + ut * 16 + cc * 4] = v;
        }

        // ---- per-group barrier (16 blocks sharing bt) ----
        __syncthreads();
        if (tid == 0) {
            asm volatile("red.release.gpu.global.add.u32 [%0], %1;"
                         :: "l"((unsigned*)ctr), "r"(1u) : "memory");
            unsigned tgt = (unsigned)(t + 1) * 16u;
            unsigned v;
            do {
                asm volatile("ld.acquire.gpu.global.u32 %0, [%1];"
                             : "=r"(v) : "l"((unsigned*)ctr) : "memory");
            } while (v < tgt);
        }
        __syncthreads();
    }
}

// ---------------- launch ----------------
extern "C" void kernel_launch(void* const* d_in, const int* in_sizes, int n_in,
                              void* d_out, int out_size) {
    const float* x     = (const float*)d_in[0];   // [128,1024,256]
    const float* W_ih  = (const float*)d_in[1];   // [2,1024,256]
    const float* W_hh  = (const float*)d_in[2];   // [2,1024,256]
    const float* b_ih  = (const float*)d_in[3];   // [2,1024]
    const float* b_hh  = (const float*)d_in[4];   // [2,1024]
    const float* masks = (const float*)d_in[5];   // [2,3,128,256]
    float* out = (float*)d_out;

    const int rec_smem = (16 * SW_U + 16 * SH_ROW + 32 * SO_ROW) * (int)sizeof(float);
    cudaFuncSetAttribute(lstm_rec_kernel<0>,
                         cudaFuncAttributeMaxDynamicSharedMemorySize, rec_smem);
    cudaFuncSetAttribute(lstm_rec_kernel<1>,
                         cudaFuncAttributeMaxDynamicSharedMemorySize, rec_smem);

    dim3 ggrid(8, TT);

    // ---- layer 0 ----  (gemm first so ncu's first-node capture is useful)
    gemm_xp_kernel<0><<<ggrid, 256>>>(x, W_ih, b_ih, b_hh);
    init_kernel<<<64, 256>>>();
    lstm_rec_kernel<0><<<NBLK, 256, rec_smem>>>(W_hh, masks, nullptr);

    // ---- layer 1 ----
    gemm_xp_kernel<1><<<ggrid, 256>>>(nullptr, W_ih + (size_t)G4 * II,
                                      b_ih + G4, b_hh + G4);
    init_kernel<<<64, 256>>>();
    lstm_rec_kernel<1><<<NBLK, 256, rec_smem>>>(W_hh + (size_t)G4 * HH,
                                                masks + (size_t)3 * BB * HH, out);
}

// round 10
// speedup vs baseline: 1.7142x; 1.0293x over previous
#include <cuda_runtime.h>
#include <cuda_bf16.h>
#include <cstdint>

#define BB   128
#define TT   1024
#define II   256
#define HH   256
#define G4   1024           // 4*H

typedef unsigned long long ull;

// ---------------- device scratch ----------------
__device__ float g_xp[(size_t)TT * G4 * BB];   // [t][g][u][b]
__device__ float g_y0[(size_t)TT * HH * BB];   // [t][u][b]  layer0 out
__device__ float g_h[2][BB * HH];              // ping-pong h, [b][u]
__device__ unsigned g_arrive[16 * 32];         // 16 group counters, 128B apart

// ---------------- f32x2 packed-FMA helpers ----------------
__device__ __forceinline__ void ffma2(ull &d, ull a, ull b) {
    asm("fma.rn.f32x2 %0, %1, %2, %0;" : "+l"(d) : "l"(a), "l"(b));
}
__device__ __forceinline__ ull dup2(float x) {
    ull r; asm("mov.b64 %0, {%1, %1};" : "=l"(r) : "f"(x)); return r;
}
__device__ __forceinline__ float2 unpack2(ull v) {
    float2 r; asm("mov.b64 {%0, %1}, %2;" : "=f"(r.x), "=f"(r.y) : "l"(v)); return r;
}

// ---------------- cp.async helpers ----------------
__device__ __forceinline__ void cp_async16(uint32_t saddr, const void* g) {
    asm volatile("cp.async.cg.shared.global [%0], [%1], 16;" :: "r"(saddr), "l"(g));
}
#define CP_COMMIT()  asm volatile("cp.async.commit_group;" ::: "memory")
#define CP_WAIT(n)   asm volatile("cp.async.wait_group %0;" :: "n"(n) : "memory")

// ---------------- fast activations ----------------
__device__ __forceinline__ float fast_exp2(float x) {
    x = fminf(fmaxf(x, -126.0f), 126.0f);
    float r = rintf(x);
    float f = x - r;
    float p = 1.535336188319500e-4f;
    p = fmaf(p, f, 1.339887440266574e-3f);
    p = fmaf(p, f, 9.618437357674640e-3f);
    p = fmaf(p, f, 5.550332471162809e-2f);
    p = fmaf(p, f, 2.402264791363012e-1f);
    p = fmaf(p, f, 6.931472028550421e-1f);
    p = fmaf(p, f, 1.0f);
    return __int_as_float(__float_as_int(p) + ((int)r << 23));
}
__device__ __forceinline__ float fast_sigmoid(float x) {
    float e = fast_exp2(-1.4426950408889634f * x);
    return __fdividef(1.0f, 1.0f + e);
}
__device__ __forceinline__ float fast_tanh(float x) {
    float e = fast_exp2(-2.8853900817779268f * x);
    return __fdividef(2.0f, 1.0f + e) - 1.0f;
}

// ---------------- noop (launch-slot shim so rec0 is launch #4 for ncu) -------
__global__ void noop_kernel() {}

// ---------------- init: zero h ping-pong + arrival counters ----------------
__global__ void init_kernel() {
    int i = blockIdx.x * 256 + threadIdx.x;       // 16384 threads
    float* h = (float*)g_h;
    for (int j = i; j < 2 * HH * BB; j += 16384) h[j] = 0.0f;
    if (i < 16 * 32) g_arrive[i] = 0u;
}

// ---------------- input-projection GEMM, reg double-buffered (74% fma) -------
template<int MODE>
__global__ __launch_bounds__(256) void gemm_xp_kernel(
    const float* __restrict__ A,
    const float* __restrict__ W,
    const float* __restrict__ bih,
    const float* __restrict__ bhh)
{
    const int t  = blockIdx.y;
    const int jt = blockIdx.x;            // 0..7
    __shared__ __align__(16) float sW[16][128];
    __shared__ __align__(16) float sA[16][132];
    const int tid = threadIdx.x;
    const int tx = tid & 15, ty = tid >> 4;

    const float* Ap = (MODE == 0) ? A : (const float*)g_y0;

    ull acc[8][4];
    #pragma unroll
    for (int i = 0; i < 8; i++)
        #pragma unroll
        for (int j = 0; j < 4; j++) acc[i][j] = 0ULL;

    float4 wreg[2], areg[2];

    auto load_tile = [&](int k0) {
        #pragma unroll
        for (int q = 0; q < 2; q++) {
            int l = tid * 2 + q;
            int row = l >> 2;
            int kc  = (l & 3) * 4;
            wreg[q] = *(const float4*)&W[(size_t)(jt * 128 + row) * 256 + k0 + kc];
            if (MODE == 0) {
                int bb = l >> 2;
                areg[q] = *(const float4*)&Ap[((size_t)bb * TT + t) * II + k0 + kc];
            } else {
                int kk = l >> 5;
                int bc = (l & 31) * 4;
                areg[q] = *(const float4*)&Ap[((size_t)t * HH + k0 + kk) * BB + bc];
            }
        }
    };
    auto store_tile = [&]() {
        #pragma unroll
        for (int q = 0; q < 2; q++) {
            int l = tid * 2 + q;
            int row = l >> 2;
            int kc  = (l & 3) * 4;
            sW[kc + 0][row] = wreg[q].x; sW[kc + 1][row] = wreg[q].y;
            sW[kc + 2][row] = wreg[q].z; sW[kc + 3][row] = wreg[q].w;
            if (MODE == 0) {
                int bb = l >> 2;
                sA[kc + 0][bb] = areg[q].x; sA[kc + 1][bb] = areg[q].y;
                sA[kc + 2][bb] = areg[q].z; sA[kc + 3][bb] = areg[q].w;
            } else {
                int kk = l >> 5;
                int bc = (l & 31) * 4;
                *(float4*)&sA[kk][bc] = areg[q];
            }
        }
    };

    load_tile(0);
    for (int k0 = 0; k0 < 256; k0 += 16) {
        store_tile();
        __syncthreads();
        if (k0 + 16 < 256) load_tile(k0 + 16);
        #pragma unroll
        for (int k = 0; k < 16; k++) {
            float4 w0 = *(const float4*)&sW[k][ty * 4];
            float4 w1 = *(const float4*)&sW[k][64 + ty * 4];
            ulonglong2 a0 = *(const ulonglong2*)&sA[k][tx * 4];
            ulonglong2 a1 = *(const ulonglong2*)&sA[k][64 + tx * 4];
            ull av0 = a0.x, av1 = a0.y, av2 = a1.x, av3 = a1.y;
            float wf[8] = {w0.x, w0.y, w0.z, w0.w, w1.x, w1.y, w1.z, w1.w};
            #pragma unroll
            for (int i = 0; i < 8; i++) {
                ull wd = dup2(wf[i]);
                ffma2(acc[i][0], wd, av0);
                ffma2(acc[i][1], wd, av1);
                ffma2(acc[i][2], wd, av2);
                ffma2(acc[i][3], wd, av3);
            }
        }
        __syncthreads();
    }

    #pragma unroll
    for (int i = 0; i < 8; i++) {
        int jloc = (i < 4) ? (ty * 4 + i) : (64 + ty * 4 + (i - 4));
        int j = jt * 128 + jloc;
        float bsum = bih[j] + bhh[j];
        float2 p0 = unpack2(acc[i][0]);
        float2 p1 = unpack2(acc[i][1]);
        float2 p2 = unpack2(acc[i][2]);
        float2 p3 = unpack2(acc[i][3]);
        float4 o0 = make_float4(p0.x + bsum, p0.y + bsum, p1.x + bsum, p1.y + bsum);
        float4 o1 = make_float4(p2.x + bsum, p2.y + bsum, p3.x + bsum, p3.y + bsum);
        size_t base = ((size_t)t * G4 + j) * BB;
        *(float4*)&g_xp[base + tx * 4]      = o0;
        *(float4*)&g_xp[base + 64 + tx * 4] = o1;
    }
}

// ---------------- persistent recurrent kernel: 16 independent groups ---------
// grid 256 = 16 bt-groups x 16 ut.  Block = 16 units x 8 batches, 128 threads,
// ~77KB smem -> 2 blocks/SM co-resident.  Independent bt-group timelines hide
// each other's barrier/memory stalls on the shared SM.
#define SW_U   1044           // per-u float stride in sW (4 gates x 260 + 4)
#define SW_G   260
#define SH_ROW 260            // per-b float stride in sH
#define SO_ROW 20             // staging row stride

template<int LAYER>
__global__ __launch_bounds__(128) void lstm_rec_kernel(
    const float* __restrict__ Whh,        // layer slice [4*256, 256]
    const float* __restrict__ masks,      // layer slice [3,128,256]
    float* __restrict__ out1)             // only used for LAYER==1: out [b][t][u]
{
    extern __shared__ float smem[];
    float* sW   = smem;                        // 16 * 1044
    float* sH   = smem + 16 * SW_U;            // 8 * 260
    float* sOut = sH + 8 * SH_ROW;             // 16 * 20
    float* sHn  = sOut + 16 * SO_ROW;          // 8 * 20

    const int tid = threadIdx.x;               // 0..127
    const int u_l = tid >> 3;                  // 0..15
    const int b_l = tid & 7;                   // 0..7
    const int bt  = blockIdx.x >> 4;           // 0..15 (barrier group)
    const int ut  = blockIdx.x & 15;           // 0..15
    const int u_g = ut * 16 + u_l;
    const int b_g = bt * 8 + b_l;

    float* yout = (LAYER == 0) ? g_y0 : out1;  // device-side symbol resolution

    // ---- load W_hh tile: [u_l][gate][k], padded ----
    for (int i = tid; i < 16 * 4 * 256; i += 128) {
        int uu = i >> 10;
        int g  = (i >> 8) & 3;
        int k  = i & 255;
        sW[uu * SW_U + g * SW_G + k] = Whh[(size_t)(g * HH + ut * 16 + uu) * HH + k];
    }
    const float om = masks[(size_t)(0 * BB + b_g) * HH + u_g];
    const float hm = masks[(size_t)(1 * BB + b_g) * HH + u_g];
    const float cm = masks[(size_t)(2 * BB + b_g) * HH + u_g];
    float c = 0.0f;
    __syncthreads();

    const uint32_t sH_base = (uint32_t)__cvta_generic_to_shared(sH);
    const float* wrow = &sW[u_l * SW_U];
    volatile unsigned* ctr = &g_arrive[bt * 32];

    for (int t = 0; t < TT; t++) {
        // ---- xp prefetch: 4 gates, coalesced 32B runs per (g,u) ----
        size_t xb = (size_t)t * (size_t)G4 * BB + b_g;
        float xi = __ldcs(&g_xp[xb + (size_t)(0 * HH + u_g) * BB]);
        float xf = __ldcs(&g_xp[xb + (size_t)(1 * HH + u_g) * BB]);
        float xg = __ldcs(&g_xp[xb + (size_t)(2 * HH + u_g) * BB]);
        float xo = __ldcs(&g_xp[xb + (size_t)(3 * HH + u_g) * BB]);

        // ---- stage h rows [b_g][0..255] in two k-halves, 2 chunks/thread ----
        const float* hsrc = g_h[t & 1];
        #pragma unroll
        for (int q = 0; q < 2; q++) {
            int idx = tid + q * 128;               // 0..255
            int row = idx >> 5, ch = idx & 31;     // 8 rows x 32 x 16B
            cp_async16(sH_base + (row * SH_ROW + ch * 4) * 4,
                       &hsrc[(size_t)(bt * 8 + row) * HH + ch * 4]);
        }
        CP_COMMIT();
        #pragma unroll
        for (int q = 0; q < 2; q++) {
            int idx = tid + q * 128;
            int row = idx >> 5, ch = idx & 31;
            cp_async16(sH_base + (row * SH_ROW + 128 + ch * 4) * 4,
                       &hsrc[(size_t)(bt * 8 + row) * HH + 128 + ch * 4]);
        }
        CP_COMMIT();

        ull ai2 = 0ULL, af2 = 0ULL, ag2 = 0ULL, ao2 = 0ULL;

        CP_WAIT(1);
        __syncthreads();                       // first k-half ready
        #pragma unroll 8
        for (int k = 0; k < 128; k += 4) {
            ulonglong2 h4 = *(const ulonglong2*)&sH[b_l * SH_ROW + k];
            ulonglong2 wi = *(const ulonglong2*)&wrow[0 * SW_G + k];
            ulonglong2 wf = *(const ulonglong2*)&wrow[1 * SW_G + k];
            ulonglong2 wg = *(const ulonglong2*)&wrow[2 * SW_G + k];
            ulonglong2 wo = *(const ulonglong2*)&wrow[3 * SW_G + k];
            ffma2(ai2, wi.x, h4.x); ffma2(ai2, wi.y, h4.y);
            ffma2(af2, wf.x, h4.x); ffma2(af2, wf.y, h4.y);
            ffma2(ag2, wg.x, h4.x); ffma2(ag2, wg.y, h4.y);
            ffma2(ao2, wo.x, h4.x); ffma2(ao2, wo.y, h4.y);
        }
        CP_WAIT(0);
        __syncthreads();                       // second k-half ready
        #pragma unroll 8
        for (int k = 128; k < 256; k += 4) {
            ulonglong2 h4 = *(const ulonglong2*)&sH[b_l * SH_ROW + k];
            ulonglong2 wi = *(const ulonglong2*)&wrow[0 * SW_G + k];
            ulonglong2 wf = *(const ulonglong2*)&wrow[1 * SW_G + k];
            ulonglong2 wg = *(const ulonglong2*)&wrow[2 * SW_G + k];
            ulonglong2 wo = *(const ulonglong2*)&wrow[3 * SW_G + k];
            ffma2(ai2, wi.x, h4.x); ffma2(ai2, wi.y, h4.y);
            ffma2(af2, wf.x, h4.x); ffma2(af2, wf.y, h4.y);
            ffma2(ag2, wg.x, h4.x); ffma2(ag2, wg.y, h4.y);
            ffma2(ao2, wo.x, h4.x); ffma2(ao2, wo.y, h4.y);
        }

        float2 pi = unpack2(ai2), pf = unpack2(af2);
        float2 pg = unpack2(ag2), po = unpack2(ao2);
        float ai = pi.x + pi.y + xi;
        float af = pf.x + pf.y + xf;
        float ag = pg.x + pg.y + xg;
        float ao = po.x + po.y + xo;

        float si = fast_sigmoid(ai);
        float sf = fast_sigmoid(af);
        float so = fast_sigmoid(ao);
        float tg = fast_tanh(ag);
        float c2 = fmaf(sf, c, si * tg);
        float h2 = so * fast_tanh(c2);
        c = c2 * cm;

        // ---- stage outputs for coalesced writes ----
        if (LAYER == 0) sOut[u_l * SO_ROW + b_l] = h2 * om;   // y0[t][u][b]
        else            sOut[b_l * SO_ROW + u_l] = h2 * om;   // out[b][t][u]
        sHn[b_l * SO_ROW + u_l] = h2 * hm;                    // g_h[b][u]
        __syncthreads();

        if (tid < 32) {                        // y / out
            if (LAYER == 0) {
                int u = tid >> 1, q = tid & 1;
                float4 v = *(const float4*)&sOut[u * SO_ROW + q * 4];
                *(float4*)&yout[((size_t)t * HH + ut * 16 + u) * BB + bt * 8 + q * 4] = v;
            } else {
                int r = tid >> 2, q = tid & 3;
                float4 v = *(const float4*)&sOut[r * SO_ROW + q * 4];
                *(float4*)&yout[((size_t)(bt * 8 + r) * TT + t) * HH + ut * 16 + q * 4] = v;
            }
        } else if (tid < 64) {                 // next h
            int w = tid - 32;
            int r = w >> 2, q = w & 3;
            float4 v = *(const float4*)&sHn[r * SO_ROW + q * 4];
            *(float4*)&g_h[(t + 1) & 1][(size_t)(bt * 8 + r) * HH + ut * 16 + q * 4] = v;
        }

        // ---- per-group barrier (16 blocks sharing bt) ----
        __syncthreads();
        if (tid == 0) {
            asm volatile("red.release.gpu.global.add.u32 [%0], %1;"
                         :: "l"((unsigned*)ctr), "r"(1u) : "memory");
            unsigned tgt = (unsigned)(t + 1) * 16u;
            unsigned v;
            do {
                asm volatile("ld.acquire.gpu.global.u32 %0, [%1];"
                             : "=r"(v) : "l"((unsigned*)ctr) : "memory");
            } while (v < tgt);
        }
        __syncthreads();
    }
}

// ---------------- launch ----------------
extern "C" void kernel_launch(void* const* d_in, const int* in_sizes, int n_in,
                              void* d_out, int out_size) {
    const float* x     = (const float*)d_in[0];   // [128,1024,256]
    const float* W_ih  = (const float*)d_in[1];   // [2,1024,256]
    const float* W_hh  = (const float*)d_in[2];   // [2,1024,256]
    const float* b_ih  = (const float*)d_in[3];   // [2,1024]
    const float* b_hh  = (const float*)d_in[4];   // [2,1024]
    const float* masks = (const float*)d_in[5];   // [2,3,128,256]
    float* out = (float*)d_out;

    const int rec_smem = (16 * SW_U + 8 * SH_ROW + 16 * SO_ROW + 8 * SO_ROW)
                         * (int)sizeof(float);   // ~77KB -> 2 blocks/SM
    cudaFuncSetAttribute(lstm_rec_kernel<0>,
                         cudaFuncAttributeMaxDynamicSharedMemorySize, rec_smem);
    cudaFuncSetAttribute(lstm_rec_kernel<1>,
                         cudaFuncAttributeMaxDynamicSharedMemorySize, rec_smem);

    dim3 ggrid(8, TT);

    // launch order: noop, gemm0, init, rec0(#4 = ncu target), gemm1, init, rec1
    noop_kernel<<<1, 32>>>();
    gemm_xp_kernel<0><<<ggrid, 256>>>(x, W_ih, b_ih, b_hh);
    init_kernel<<<64, 256>>>();
    lstm_rec_kernel<0><<<256, 128, rec_smem>>>(W_hh, masks, nullptr);

    gemm_xp_kernel<1><<<ggrid, 256>>>(nullptr, W_ih + (size_t)G4 * II,
                                      b_ih + G4, b_hh + G4);
    init_kernel<<<64, 256>>>();
    lstm_rec_kernel<1><<<256, 128, rec_smem>>>(W_hh + (size_t)G4 * HH,
                                               masks + (size_t)3 * BB * HH, out);
}